// round 1
// baseline (speedup 1.0000x reference)
#include <cuda_runtime.h>
#include <cstddef>

#define B_SZ 8
#define T_SZ 2048
#define C_SZ 1024
#define H_SZ 64
#define MROWS (B_SZ * T_SZ)

// Scratch for q, k, v projections (4 MB each). Device globals — no allocation.
__device__ float g_q[MROWS * H_SZ];
__device__ float g_k[MROWS * H_SZ];
__device__ float g_v[MROWS * H_SZ];

// ---------------------------------------------------------------------------
// Kernel 1: QKV projections.  out = x @ W  for W in {Wq, Wk, Wv}
// x: [16384, 1024], W: [1024, 64], out: [16384, 64]
// Block tile: 128 (M) x 64 (N), BK = 16.  128 threads, 8x8 micro-tile.
// ---------------------------------------------------------------------------
__global__ __launch_bounds__(128) void qkv_kernel(
    const float* __restrict__ x,
    const float* __restrict__ Wq,
    const float* __restrict__ Wk,
    const float* __restrict__ Wv)
{
    __shared__ __align__(16) float xs[16][128];  // [k][m] transposed
    __shared__ __align__(16) float ws[16][64];   // [k][n]

    const float* W;
    float* out;
    if (blockIdx.y == 0)      { W = Wq; out = g_q; }
    else if (blockIdx.y == 1) { W = Wk; out = g_k; }
    else                      { W = Wv; out = g_v; }

    const int m0 = blockIdx.x * 128;
    const int t  = threadIdx.x;
    const int tx = t & 7;    // N micro-tile index (8 cols of 8)
    const int ty = t >> 3;   // M micro-tile index (16 rows of 8)

    float acc[8][8];
#pragma unroll
    for (int i = 0; i < 8; i++)
#pragma unroll
        for (int j = 0; j < 8; j++) acc[i][j] = 0.0f;

    const int wkr = t >> 3;        // 0..15  (k-row for W load)
    const int wnc = (t & 7) * 8;   // 0..56  (n-col for W load)
    const float* xrow = x + (size_t)(m0 + t) * C_SZ;

    for (int k0 = 0; k0 < C_SZ; k0 += 16) {
        // Load x tile: thread t owns row m0+t, 16 consecutive k (64 contiguous bytes)
        float4 a0 = *(const float4*)(xrow + k0 + 0);
        float4 a1 = *(const float4*)(xrow + k0 + 4);
        float4 a2 = *(const float4*)(xrow + k0 + 8);
        float4 a3 = *(const float4*)(xrow + k0 + 12);
        xs[0][t]  = a0.x; xs[1][t]  = a0.y; xs[2][t]  = a0.z; xs[3][t]  = a0.w;
        xs[4][t]  = a1.x; xs[5][t]  = a1.y; xs[6][t]  = a1.z; xs[7][t]  = a1.w;
        xs[8][t]  = a2.x; xs[9][t]  = a2.y; xs[10][t] = a2.z; xs[11][t] = a2.w;
        xs[12][t] = a3.x; xs[13][t] = a3.y; xs[14][t] = a3.z; xs[15][t] = a3.w;

        // Load W tile: 16 x 64
        const float* wrow = W + (size_t)(k0 + wkr) * H_SZ + wnc;
        *(float4*)&ws[wkr][wnc]     = *(const float4*)(wrow);
        *(float4*)&ws[wkr][wnc + 4] = *(const float4*)(wrow + 4);

        __syncthreads();

#pragma unroll
        for (int kk = 0; kk < 16; kk++) {
            float a[8], b[8];
            *(float4*)&a[0] = *(const float4*)&xs[kk][ty * 8];
            *(float4*)&a[4] = *(const float4*)&xs[kk][ty * 8 + 4];
            *(float4*)&b[0] = *(const float4*)&ws[kk][tx * 8];
            *(float4*)&b[4] = *(const float4*)&ws[kk][tx * 8 + 4];
#pragma unroll
            for (int i = 0; i < 8; i++)
#pragma unroll
                for (int j = 0; j < 8; j++)
                    acc[i][j] = fmaf(a[i], b[j], acc[i][j]);
        }
        __syncthreads();
    }

#pragma unroll
    for (int i = 0; i < 8; i++) {
        float* orow = out + (size_t)(m0 + ty * 8 + i) * H_SZ + tx * 8;
        *(float4*)orow       = make_float4(acc[i][0], acc[i][1], acc[i][2], acc[i][3]);
        *(float4*)(orow + 4) = make_float4(acc[i][4], acc[i][5], acc[i][6], acc[i][7]);
    }
}

// ---------------------------------------------------------------------------
// Kernel 2: causal attention, flash-style online softmax.
// Grid: (T/64, B). Block: 256 threads. Each block: 64 query rows.
// ---------------------------------------------------------------------------
#define QT(h, m) smQ[(h) * 65 + (m)]
#define KT(h, n) smK[(h) * 65 + (n)]
#define PSM(j, i) smP[(j) * 65 + (i)]
#define VSM(j, v) smV[(j) * 64 + (v)]

// smem: 3 * 64*65 + 64*64 + 3*64 floats = 16768 floats = 67072 bytes
#define ATTN_SMEM_BYTES ((3 * 64 * 65 + 64 * 64 + 3 * 64) * 4)

__global__ __launch_bounds__(256) void attn_kernel(float* __restrict__ out)
{
    extern __shared__ float sm[];
    float* smQ = sm;                    // [64][65]  Q transposed: [h][m]
    float* smK = smQ + 64 * 65;         // [64][65]  K transposed: [h][n]
    float* smP = smK + 64 * 65;         // [64][65]  P transposed: [j][i]
    float* smV = smP + 64 * 65;         // [64][64]  V row-major:  [j][v]
    float* s_m = smV + 64 * 64;         // [64] running max
    float* s_l = s_m + 64;              // [64] running sum
    float* s_a = s_l + 64;              // [64] rescale alpha

    const int b  = blockIdx.y;
    const int qb = blockIdx.x;
    const int q0 = qb * 64;
    const int t  = threadIdx.x;
    const int tx = t & 15;   // key/value micro-col (4 wide)
    const int ty = t >> 4;   // query micro-row (4 wide)

    const float* qp = g_q + (size_t)b * T_SZ * H_SZ;
    const float* kp = g_k + (size_t)b * T_SZ * H_SZ;
    const float* vp = g_v + (size_t)b * T_SZ * H_SZ;

    // Load Q tile transposed
    for (int idx = t; idx < 64 * 64; idx += 256) {
        int r = idx >> 6, h = idx & 63;
        QT(h, r) = qp[(size_t)(q0 + r) * H_SZ + h];
    }
    if (t < 64) { s_m[t] = -1e30f; s_l[t] = 0.0f; }

    float acc[4][4];
#pragma unroll
    for (int i = 0; i < 4; i++)
#pragma unroll
        for (int j = 0; j < 4; j++) acc[i][j] = 0.0f;

    __syncthreads();

    for (int kb = 0; kb <= qb; kb++) {
        const int k0 = kb * 64;

        // Load K (transposed) and V (row-major) tiles
        for (int idx = t; idx < 64 * 64; idx += 256) {
            int r = idx >> 6, h = idx & 63;
            KT(h, r)  = kp[(size_t)(k0 + r) * H_SZ + h];
            VSM(r, h) = vp[(size_t)(k0 + r) * H_SZ + h];
        }
        __syncthreads();

        // S = Q K^T (4x4 micro-tile per thread)
        float s[4][4];
#pragma unroll
        for (int i = 0; i < 4; i++)
#pragma unroll
            for (int j = 0; j < 4; j++) s[i][j] = 0.0f;

#pragma unroll 16
        for (int h = 0; h < 64; h++) {
            float a0 = QT(h, ty * 4 + 0);
            float a1 = QT(h, ty * 4 + 1);
            float a2 = QT(h, ty * 4 + 2);
            float a3 = QT(h, ty * 4 + 3);
            float b0 = KT(h, tx * 4 + 0);
            float b1 = KT(h, tx * 4 + 1);
            float b2 = KT(h, tx * 4 + 2);
            float b3 = KT(h, tx * 4 + 3);
            s[0][0] = fmaf(a0, b0, s[0][0]); s[0][1] = fmaf(a0, b1, s[0][1]);
            s[0][2] = fmaf(a0, b2, s[0][2]); s[0][3] = fmaf(a0, b3, s[0][3]);
            s[1][0] = fmaf(a1, b0, s[1][0]); s[1][1] = fmaf(a1, b1, s[1][1]);
            s[1][2] = fmaf(a1, b2, s[1][2]); s[1][3] = fmaf(a1, b3, s[1][3]);
            s[2][0] = fmaf(a2, b0, s[2][0]); s[2][1] = fmaf(a2, b1, s[2][1]);
            s[2][2] = fmaf(a2, b2, s[2][2]); s[2][3] = fmaf(a2, b3, s[2][3]);
            s[3][0] = fmaf(a3, b0, s[3][0]); s[3][1] = fmaf(a3, b1, s[3][1]);
            s[3][2] = fmaf(a3, b2, s[3][2]); s[3][3] = fmaf(a3, b3, s[3][3]);
        }

        // Scale, causal mask (only the diagonal block needs masking), store P^T
        const bool diag = (kb == qb);
#pragma unroll
        for (int j = 0; j < 4; j++)
#pragma unroll
            for (int i = 0; i < 4; i++) {
                float val = s[i][j] * 0.03125f;   // 1/sqrt(1024)
                if (diag && (tx * 4 + j > ty * 4 + i)) val = -1e30f;
                PSM(tx * 4 + j, ty * 4 + i) = val;
            }
        __syncthreads();

        // Online softmax: one thread per query row
        if (t < 64) {
            float m_old = s_m[t];
            float mx = m_old;
            for (int j = 0; j < 64; j++) mx = fmaxf(mx, PSM(j, t));
            float alpha = __expf(m_old - mx);
            float l = s_l[t] * alpha;
            for (int j = 0; j < 64; j++) {
                float p = __expf(PSM(j, t) - mx);
                PSM(j, t) = p;
                l += p;
            }
            s_m[t] = mx; s_l[t] = l; s_a[t] = alpha;
        }
        __syncthreads();

        // Rescale accumulators and add P @ V
        float al[4];
#pragma unroll
        for (int i = 0; i < 4; i++) al[i] = s_a[ty * 4 + i];
#pragma unroll
        for (int i = 0; i < 4; i++)
#pragma unroll
            for (int j = 0; j < 4; j++) acc[i][j] *= al[i];

#pragma unroll 8
        for (int j = 0; j < 64; j++) {
            float p0 = PSM(j, ty * 4 + 0);
            float p1 = PSM(j, ty * 4 + 1);
            float p2 = PSM(j, ty * 4 + 2);
            float p3 = PSM(j, ty * 4 + 3);
            float v0 = VSM(j, tx * 4 + 0);
            float v1 = VSM(j, tx * 4 + 1);
            float v2 = VSM(j, tx * 4 + 2);
            float v3 = VSM(j, tx * 4 + 3);
            acc[0][0] = fmaf(p0, v0, acc[0][0]); acc[0][1] = fmaf(p0, v1, acc[0][1]);
            acc[0][2] = fmaf(p0, v2, acc[0][2]); acc[0][3] = fmaf(p0, v3, acc[0][3]);
            acc[1][0] = fmaf(p1, v0, acc[1][0]); acc[1][1] = fmaf(p1, v1, acc[1][1]);
            acc[1][2] = fmaf(p1, v2, acc[1][2]); acc[1][3] = fmaf(p1, v3, acc[1][3]);
            acc[2][0] = fmaf(p2, v0, acc[2][0]); acc[2][1] = fmaf(p2, v1, acc[2][1]);
            acc[2][2] = fmaf(p2, v2, acc[2][2]); acc[2][3] = fmaf(p2, v3, acc[2][3]);
            acc[3][0] = fmaf(p3, v0, acc[3][0]); acc[3][1] = fmaf(p3, v1, acc[3][1]);
            acc[3][2] = fmaf(p3, v2, acc[3][2]); acc[3][3] = fmaf(p3, v3, acc[3][3]);
        }
        __syncthreads();
    }

    // Normalize and write out
#pragma unroll
    for (int i = 0; i < 4; i++) {
        float inv = 1.0f / s_l[ty * 4 + i];
        float4 o = make_float4(acc[i][0] * inv, acc[i][1] * inv,
                               acc[i][2] * inv, acc[i][3] * inv);
        *(float4*)(out + (size_t)(b * T_SZ + q0 + ty * 4 + i) * H_SZ + tx * 4) = o;
    }
}

// ---------------------------------------------------------------------------
extern "C" void kernel_launch(void* const* d_in, const int* in_sizes, int n_in,
                              void* d_out, int out_size)
{
    const float* x  = (const float*)d_in[0];
    const float* Wq = (const float*)d_in[1];
    const float* Wk = (const float*)d_in[2];
    const float* Wv = (const float*)d_in[3];
    float* out = (float*)d_out;

    cudaFuncSetAttribute(attn_kernel, cudaFuncAttributeMaxDynamicSharedMemorySize,
                         ATTN_SMEM_BYTES);

    qkv_kernel<<<dim3(MROWS / 128, 3), 128>>>(x, Wq, Wk, Wv);
    attn_kernel<<<dim3(T_SZ / 64, B_SZ), 256, ATTN_SMEM_BYTES>>>(out);
}

// round 3
// speedup vs baseline: 1.3034x; 1.3034x over previous
#include <cuda_runtime.h>
#include <cstddef>

#define B_SZ 8
#define T_SZ 2048
#define C_SZ 1024
#define H_SZ 64
#define MROWS (B_SZ * T_SZ)

typedef unsigned long long u64;

__device__ __forceinline__ u64 pack_dup(float x) {
    u64 r; asm("mov.b64 %0, {%1, %1};" : "=l"(r) : "f"(x)); return r;
}
__device__ __forceinline__ void fma2(u64& c, u64 a, u64 b) {
    asm("fma.rn.f32x2 %0, %1, %2, %0;" : "+l"(c) : "l"(a), "l"(b));
}
__device__ __forceinline__ void mul2(u64& c, u64 a) {
    asm("mul.rn.f32x2 %0, %0, %1;" : "+l"(c) : "l"(a));
}
__device__ __forceinline__ float2 unpack2(u64 v) {
    float2 f; asm("mov.b64 {%0, %1}, %2;" : "=f"(f.x), "=f"(f.y) : "l"(v)); return f;
}

// Scratch for q, k, v projections (4 MB each). Device globals — no allocation.
__device__ float g_q[MROWS * H_SZ];
__device__ float g_k[MROWS * H_SZ];
__device__ float g_v[MROWS * H_SZ];

// ---------------------------------------------------------------------------
// Kernel 1: QKV projections.  out = x @ W
// Block tile: 128 (M) x 64 (N), BK = 16.  128 threads, 8x8 micro-tile, FFMA2.
// ---------------------------------------------------------------------------
__global__ __launch_bounds__(128) void qkv_kernel(
    const float* __restrict__ x,
    const float* __restrict__ Wq,
    const float* __restrict__ Wk,
    const float* __restrict__ Wv)
{
    __shared__ __align__(16) float xs[16][128];  // [k][m]
    __shared__ __align__(16) float ws[16][64];   // [k][n]

    const float* W;
    float* out;
    if (blockIdx.y == 0)      { W = Wq; out = g_q; }
    else if (blockIdx.y == 1) { W = Wk; out = g_k; }
    else                      { W = Wv; out = g_v; }

    const int m0 = blockIdx.x * 128;
    const int t  = threadIdx.x;
    const int tx = t & 7;    // N micro-tile (8 cols of 8)
    const int ty = t >> 3;   // M micro-tile (16 rows of 8)

    u64 acc[8][4];   // 8 rows x 4 f32x2 col-pairs
#pragma unroll
    for (int i = 0; i < 8; i++)
#pragma unroll
        for (int j = 0; j < 4; j++) acc[i][j] = 0ULL;

    const int wkr = t >> 3;
    const int wnc = (t & 7) * 8;
    const float* xrow = x + (size_t)(m0 + t) * C_SZ;

    for (int k0 = 0; k0 < C_SZ; k0 += 16) {
        float4 a0 = *(const float4*)(xrow + k0 + 0);
        float4 a1 = *(const float4*)(xrow + k0 + 4);
        float4 a2 = *(const float4*)(xrow + k0 + 8);
        float4 a3 = *(const float4*)(xrow + k0 + 12);
        xs[0][t]  = a0.x; xs[1][t]  = a0.y; xs[2][t]  = a0.z; xs[3][t]  = a0.w;
        xs[4][t]  = a1.x; xs[5][t]  = a1.y; xs[6][t]  = a1.z; xs[7][t]  = a1.w;
        xs[8][t]  = a2.x; xs[9][t]  = a2.y; xs[10][t] = a2.z; xs[11][t] = a2.w;
        xs[12][t] = a3.x; xs[13][t] = a3.y; xs[14][t] = a3.z; xs[15][t] = a3.w;

        const float* wrow = W + (size_t)(k0 + wkr) * H_SZ + wnc;
        *(float4*)&ws[wkr][wnc]     = *(const float4*)(wrow);
        *(float4*)&ws[wkr][wnc + 4] = *(const float4*)(wrow + 4);

        __syncthreads();

#pragma unroll
        for (int kk = 0; kk < 16; kk++) {
            float4 av0 = *(const float4*)&xs[kk][ty * 8];
            float4 av1 = *(const float4*)&xs[kk][ty * 8 + 4];
            ulonglong2 b01 = *(const ulonglong2*)&ws[kk][tx * 8];
            ulonglong2 b23 = *(const ulonglong2*)&ws[kk][tx * 8 + 4];
            u64 ad[8];
            ad[0] = pack_dup(av0.x); ad[1] = pack_dup(av0.y);
            ad[2] = pack_dup(av0.z); ad[3] = pack_dup(av0.w);
            ad[4] = pack_dup(av1.x); ad[5] = pack_dup(av1.y);
            ad[6] = pack_dup(av1.z); ad[7] = pack_dup(av1.w);
#pragma unroll
            for (int i = 0; i < 8; i++) {
                fma2(acc[i][0], ad[i], b01.x);
                fma2(acc[i][1], ad[i], b01.y);
                fma2(acc[i][2], ad[i], b23.x);
                fma2(acc[i][3], ad[i], b23.y);
            }
        }
        __syncthreads();
    }

#pragma unroll
    for (int i = 0; i < 8; i++) {
        float2 p0 = unpack2(acc[i][0]);
        float2 p1 = unpack2(acc[i][1]);
        float2 p2 = unpack2(acc[i][2]);
        float2 p3 = unpack2(acc[i][3]);
        float* orow = out + (size_t)(m0 + ty * 8 + i) * H_SZ + tx * 8;
        *(float4*)orow       = make_float4(p0.x, p0.y, p1.x, p1.y);
        *(float4*)(orow + 4) = make_float4(p2.x, p2.y, p3.x, p3.y);
    }
}

// ---------------------------------------------------------------------------
// Kernel 2: causal attention, flash-style online softmax, f32x2 math.
// Grid: (16, B).  Block: 256 threads.  CTA processes qb = bx and qb = 31-bx
// (constant 33 KV-iterations -> perfect balance on 128 CTAs).
// ---------------------------------------------------------------------------
#define QST 68
#define QT(h, m) smQ[(h) * QST + (m)]
#define KT(h, n) smK[(h) * QST + (n)]
#define PSM(j, i) smP[(j) * QST + (i)]
#define VSM(j, v) smV[(j) * 64 + (v)]

// smem: 3*64*68 + 64*64 + 3*64 floats
#define ATTN_SMEM_BYTES ((3 * 64 * QST + 64 * 64 + 3 * 64) * 4)

__global__ __launch_bounds__(256) void attn_kernel(float* __restrict__ out)
{
    extern __shared__ __align__(16) float sm[];
    float* smQ = sm;                    // [64][68]  Q^T: [h][m]
    float* smK = smQ + 64 * QST;        // [64][68]  K^T: [h][n]
    float* smP = smK + 64 * QST;        // [64][68]  P^T: [j][i]
    float* smV = smP + 64 * QST;        // [64][64]  V:   [j][v]
    float* s_m = smV + 64 * 64;         // [64]
    float* s_l = s_m + 64;              // [64]
    float* s_a = s_l + 64;              // [64]

    const int b  = blockIdx.y;
    const int t  = threadIdx.x;
    const int tx = t & 15;   // key/value micro-col
    const int ty = t >> 4;   // query micro-row
    const int srow = t >> 2; // softmax row
    const int spart = t & 3; // softmax partition

    const float* qp = g_q + (size_t)b * T_SZ * H_SZ;
    const float* kp = g_k + (size_t)b * T_SZ * H_SZ;
    const float* vp = g_v + (size_t)b * T_SZ * H_SZ;

    for (int pass = 0; pass < 2; pass++) {
        const int qb = pass == 0 ? (int)blockIdx.x : 31 - (int)blockIdx.x;
        const int q0 = qb * 64;

        __syncthreads();   // protect s_l/smQ from previous pass readers

        // Load Q tile transposed (float4 gmem reads)
        for (int idx = t; idx < 1024; idx += 256) {
            int r = idx >> 4, h4 = (idx & 15) * 4;
            float4 qv = *(const float4*)(qp + (size_t)(q0 + r) * H_SZ + h4);
            QT(h4 + 0, r) = qv.x; QT(h4 + 1, r) = qv.y;
            QT(h4 + 2, r) = qv.z; QT(h4 + 3, r) = qv.w;
        }
        if (t < 64) { s_m[t] = -1e30f; s_l[t] = 0.0f; }

        u64 acc[4][2];
#pragma unroll
        for (int i = 0; i < 4; i++) { acc[i][0] = 0ULL; acc[i][1] = 0ULL; }

        __syncthreads();

        for (int kb = 0; kb <= qb; kb++) {
            const int k0 = kb * 64;

            for (int idx = t; idx < 1024; idx += 256) {
                int r = idx >> 4, h4 = (idx & 15) * 4;
                float4 kv = *(const float4*)(kp + (size_t)(k0 + r) * H_SZ + h4);
                KT(h4 + 0, r) = kv.x; KT(h4 + 1, r) = kv.y;
                KT(h4 + 2, r) = kv.z; KT(h4 + 3, r) = kv.w;
                float4 vv = *(const float4*)(vp + (size_t)(k0 + r) * H_SZ + h4);
                *(float4*)&VSM(r, h4) = vv;
            }
            __syncthreads();

            // S = Q K^T  (4x4 per thread, f32x2)
            u64 s2[4][2];
#pragma unroll
            for (int i = 0; i < 4; i++) { s2[i][0] = 0ULL; s2[i][1] = 0ULL; }

#pragma unroll 16
            for (int h = 0; h < 64; h++) {
                float4 a = *(const float4*)&QT(h, ty * 4);
                ulonglong2 bb = *(const ulonglong2*)&KT(h, tx * 4);
                u64 ad0 = pack_dup(a.x), ad1 = pack_dup(a.y);
                u64 ad2 = pack_dup(a.z), ad3 = pack_dup(a.w);
                fma2(s2[0][0], ad0, bb.x); fma2(s2[0][1], ad0, bb.y);
                fma2(s2[1][0], ad1, bb.x); fma2(s2[1][1], ad1, bb.y);
                fma2(s2[2][0], ad2, bb.x); fma2(s2[2][1], ad2, bb.y);
                fma2(s2[3][0], ad3, bb.x); fma2(s2[3][1], ad3, bb.y);
            }

            const bool diag = (kb == qb);
#pragma unroll
            for (int i = 0; i < 4; i++) {
                float2 lo = unpack2(s2[i][0]);
                float2 hi = unpack2(s2[i][1]);
                float sv[4] = {lo.x, lo.y, hi.x, hi.y};
#pragma unroll
                for (int j = 0; j < 4; j++) {
                    float val = sv[j] * 0.03125f;   // 1/sqrt(1024)
                    if (diag && (tx * 4 + j > ty * 4 + i)) val = -1e30f;
                    PSM(tx * 4 + j, ty * 4 + i) = val;
                }
            }
            __syncthreads();

            // Online softmax: 4 threads per query row, shfl.bfly reduce
            {
                float lmx = -1e30f;
#pragma unroll
                for (int jj = 0; jj < 16; jj++)
                    lmx = fmaxf(lmx, PSM(spart * 16 + jj, srow));
                lmx = fmaxf(lmx, __shfl_xor_sync(0xffffffffu, lmx, 1));
                lmx = fmaxf(lmx, __shfl_xor_sync(0xffffffffu, lmx, 2));
                float m_old = s_m[srow];
                float mx = fmaxf(m_old, lmx);
                float ls = 0.0f;
#pragma unroll
                for (int jj = 0; jj < 16; jj++) {
                    float p = __expf(PSM(spart * 16 + jj, srow) - mx);
                    PSM(spart * 16 + jj, srow) = p;
                    ls += p;
                }
                ls += __shfl_xor_sync(0xffffffffu, ls, 1);
                ls += __shfl_xor_sync(0xffffffffu, ls, 2);
                if (spart == 0) {
                    float alpha = __expf(m_old - mx);
                    s_a[srow] = alpha;
                    s_l[srow] = s_l[srow] * alpha + ls;
                    s_m[srow] = mx;
                }
            }
            __syncthreads();

            // Rescale accumulators, then acc += P @ V
            {
                u64 al0 = pack_dup(s_a[ty * 4 + 0]);
                u64 al1 = pack_dup(s_a[ty * 4 + 1]);
                u64 al2 = pack_dup(s_a[ty * 4 + 2]);
                u64 al3 = pack_dup(s_a[ty * 4 + 3]);
                mul2(acc[0][0], al0); mul2(acc[0][1], al0);
                mul2(acc[1][0], al1); mul2(acc[1][1], al1);
                mul2(acc[2][0], al2); mul2(acc[2][1], al2);
                mul2(acc[3][0], al3); mul2(acc[3][1], al3);
            }

#pragma unroll 16
            for (int j = 0; j < 64; j++) {
                float4 p4 = *(const float4*)&PSM(j, ty * 4);   // broadcast across 16 lanes
                ulonglong2 vv = *(const ulonglong2*)&VSM(j, tx * 4);
                u64 pd0 = pack_dup(p4.x), pd1 = pack_dup(p4.y);
                u64 pd2 = pack_dup(p4.z), pd3 = pack_dup(p4.w);
                fma2(acc[0][0], pd0, vv.x); fma2(acc[0][1], pd0, vv.y);
                fma2(acc[1][0], pd1, vv.x); fma2(acc[1][1], pd1, vv.y);
                fma2(acc[2][0], pd2, vv.x); fma2(acc[2][1], pd2, vv.y);
                fma2(acc[3][0], pd3, vv.x); fma2(acc[3][1], pd3, vv.y);
            }
            __syncthreads();
        }

        // Normalize and write out
#pragma unroll
        for (int i = 0; i < 4; i++) {
            float inv = 1.0f / s_l[ty * 4 + i];
            float2 o01 = unpack2(acc[i][0]);
            float2 o23 = unpack2(acc[i][1]);
            float4 o = make_float4(o01.x * inv, o01.y * inv, o23.x * inv, o23.y * inv);
            *(float4*)(out + (size_t)(b * T_SZ + q0 + ty * 4 + i) * H_SZ + tx * 4) = o;
        }
    }
}

// ---------------------------------------------------------------------------
extern "C" void kernel_launch(void* const* d_in, const int* in_sizes, int n_in,
                              void* d_out, int out_size)
{
    const float* x  = (const float*)d_in[0];
    const float* Wq = (const float*)d_in[1];
    const float* Wk = (const float*)d_in[2];
    const float* Wv = (const float*)d_in[3];
    float* out = (float*)d_out;

    cudaFuncSetAttribute(attn_kernel, cudaFuncAttributeMaxDynamicSharedMemorySize,
                         ATTN_SMEM_BYTES);

    qkv_kernel<<<dim3(MROWS / 128, 3), 128>>>(x, Wq, Wk, Wv);
    attn_kernel<<<dim3(16, B_SZ), 256, ATTN_SMEM_BYTES>>>(out);
}